// round 1
// baseline (speedup 1.0000x reference)
#include <cuda_runtime.h>

// Problem constants
#define Bq 8
#define Sq 4096
#define Dq 768
#define Hq 12
#define DHq 64
#define Mq (Bq * Sq)          // 32768 rows

// ---------------------------------------------------------------------------
// Scratch (device globals: allocation-free per harness rules)
// ---------------------------------------------------------------------------
__device__ float g_Q[(size_t)Mq * Dq];
__device__ float g_K[(size_t)Mq * Dq];
__device__ float g_V[(size_t)Mq * Dq];
__device__ float g_att[(size_t)Mq * Dq];
__device__ float g_Y[(size_t)Mq * Dq];

// ---------------------------------------------------------------------------
// GEMM 1: QKV.  C[m, n] over n in [0, 2304): sel = n/768 picks Wq/Wk/Wv.
// Classic 128x128x8 fp32 SIMT tile, 256 threads, 8x8 per-thread microtile.
// ---------------------------------------------------------------------------
__global__ void __launch_bounds__(256) qkv_gemm_kernel(
    const float* __restrict__ x,
    const float* __restrict__ Wq, const float* __restrict__ bq,
    const float* __restrict__ Wk, const float* __restrict__ bk,
    const float* __restrict__ Wv, const float* __restrict__ bv)
{
    __shared__ float As[8][128];
    __shared__ float Bs[8][128];

    const int bn = blockIdx.x;            // 0..17
    const int bm = blockIdx.y;            // 0..255
    const int sel = (bn * 128) / 768;     // 0: Q, 1: K, 2: V
    const int n0  = (bn * 128) % 768;
    const float* W   = (sel == 0) ? Wq : (sel == 1) ? Wk : Wv;
    const float* bia = (sel == 0) ? bq : (sel == 1) ? bk : bv;
    float* out       = (sel == 0) ? g_Q : (sel == 1) ? g_K : g_V;

    const int tid   = threadIdx.x;
    const int a_row = tid >> 1;           // 0..127
    const int a_c4  = (tid & 1) * 4;      // 0 or 4
    const int b_row = tid >> 5;           // 0..7
    const int b_c4  = (tid & 31) * 4;     // 0..124
    const int ty    = tid >> 4;           // 0..15
    const int tx    = tid & 15;           // 0..15

    const float* Ag = x + (size_t)(bm * 128 + a_row) * Dq + a_c4;
    const float* Bg = W + (size_t)b_row * Dq + n0 + b_c4;

    float acc[8][8];
    #pragma unroll
    for (int i = 0; i < 8; i++)
        #pragma unroll
        for (int j = 0; j < 8; j++) acc[i][j] = 0.f;

    for (int k0 = 0; k0 < Dq; k0 += 8) {
        float4 av = *(const float4*)(Ag + k0);
        As[a_c4 + 0][a_row] = av.x;
        As[a_c4 + 1][a_row] = av.y;
        As[a_c4 + 2][a_row] = av.z;
        As[a_c4 + 3][a_row] = av.w;
        *(float4*)&Bs[b_row][b_c4] = *(const float4*)(Bg + (size_t)k0 * Dq);
        __syncthreads();
        #pragma unroll
        for (int kk = 0; kk < 8; kk++) {
            float af[8], bf[8];
            #pragma unroll
            for (int i = 0; i < 8; i++) af[i] = As[kk][ty * 8 + i];
            #pragma unroll
            for (int j = 0; j < 8; j++) bf[j] = Bs[kk][tx * 8 + j];
            #pragma unroll
            for (int i = 0; i < 8; i++)
                #pragma unroll
                for (int j = 0; j < 8; j++)
                    acc[i][j] += af[i] * bf[j];
        }
        __syncthreads();
    }

    #pragma unroll
    for (int i = 0; i < 8; i++) {
        const int m = bm * 128 + ty * 8 + i;
        float* orow = out + (size_t)m * Dq + n0 + tx * 8;
        #pragma unroll
        for (int j = 0; j < 8; j += 4) {
            const int n = n0 + tx * 8 + j;
            float4 v;
            v.x = acc[i][j + 0] + bia[n + 0];
            v.y = acc[i][j + 1] + bia[n + 1];
            v.z = acc[i][j + 2] + bia[n + 2];
            v.w = acc[i][j + 3] + bia[n + 3];
            *(float4*)(orow + j) = v;
        }
    }
}

// ---------------------------------------------------------------------------
// GEMM 2: out = g_att @ Wo + bo + x  -> g_Y   (residual fused in epilogue)
// ---------------------------------------------------------------------------
__global__ void __launch_bounds__(256) out_gemm_kernel(
    const float* __restrict__ xres,
    const float* __restrict__ Wo, const float* __restrict__ bo)
{
    __shared__ float As[8][128];
    __shared__ float Bs[8][128];

    const int bn = blockIdx.x;            // 0..5
    const int bm = blockIdx.y;            // 0..255
    const int n0 = bn * 128;

    const int tid   = threadIdx.x;
    const int a_row = tid >> 1;
    const int a_c4  = (tid & 1) * 4;
    const int b_row = tid >> 5;
    const int b_c4  = (tid & 31) * 4;
    const int ty    = tid >> 4;
    const int tx    = tid & 15;

    const float* Ag = g_att + (size_t)(bm * 128 + a_row) * Dq + a_c4;
    const float* Bg = Wo + (size_t)b_row * Dq + n0 + b_c4;

    float acc[8][8];
    #pragma unroll
    for (int i = 0; i < 8; i++)
        #pragma unroll
        for (int j = 0; j < 8; j++) acc[i][j] = 0.f;

    for (int k0 = 0; k0 < Dq; k0 += 8) {
        float4 av = *(const float4*)(Ag + k0);
        As[a_c4 + 0][a_row] = av.x;
        As[a_c4 + 1][a_row] = av.y;
        As[a_c4 + 2][a_row] = av.z;
        As[a_c4 + 3][a_row] = av.w;
        *(float4*)&Bs[b_row][b_c4] = *(const float4*)(Bg + (size_t)k0 * Dq);
        __syncthreads();
        #pragma unroll
        for (int kk = 0; kk < 8; kk++) {
            float af[8], bf[8];
            #pragma unroll
            for (int i = 0; i < 8; i++) af[i] = As[kk][ty * 8 + i];
            #pragma unroll
            for (int j = 0; j < 8; j++) bf[j] = Bs[kk][tx * 8 + j];
            #pragma unroll
            for (int i = 0; i < 8; i++)
                #pragma unroll
                for (int j = 0; j < 8; j++)
                    acc[i][j] += af[i] * bf[j];
        }
        __syncthreads();
    }

    #pragma unroll
    for (int i = 0; i < 8; i++) {
        const int m = bm * 128 + ty * 8 + i;
        const size_t rowb = (size_t)m * Dq + n0 + tx * 8;
        #pragma unroll
        for (int j = 0; j < 8; j += 4) {
            const int n = n0 + tx * 8 + j;
            float4 xr = *(const float4*)(xres + rowb + j);
            float4 v;
            v.x = acc[i][j + 0] + bo[n + 0] + xr.x;
            v.y = acc[i][j + 1] + bo[n + 1] + xr.y;
            v.z = acc[i][j + 2] + bo[n + 2] + xr.z;
            v.w = acc[i][j + 3] + bo[n + 3] + xr.w;
            *(float4*)(g_Y + rowb + j) = v;
        }
    }
}

// ---------------------------------------------------------------------------
// Banded attention: per (b, h, tile of 128 s-positions).
// K/V staged transposed in smem (dim-major, stride 133 -> conflict-free).
// Out-of-range taps use bias values (padded x=0 -> k=bk, v=bv).
// ---------------------------------------------------------------------------
#define ATT_TS 128
#define ATT_LD 133    // smem position-stride (odd, coprime with 32 banks)

__global__ void __launch_bounds__(128) attn_kernel(
    const float* __restrict__ bk, const float* __restrict__ bv)
{
    extern __shared__ float sm[];
    float* Ks = sm;
    float* Vs = sm + DHq * ATT_LD;

    const int bh = blockIdx.y;
    const int b  = bh / Hq;
    const int h  = bh % Hq;
    const int s0 = blockIdx.x * ATT_TS;

    const size_t base = ((size_t)b * Sq) * Dq + h * DHq;
    const float* Kg = g_K + base;
    const float* Vg = g_V + base;

    const int tid = threadIdx.x;
    // Stage K/V halo tiles [s0-2, s0+TS+2) transposed: Ks[d * LD + pos]
    for (int idx = tid; idx < (ATT_TS + 4) * DHq; idx += 128) {
        const int r = idx >> 6;    // halo position 0..131
        const int c = idx & 63;    // dim
        const int gs = s0 - 2 + r;
        float kv, vv;
        if (gs >= 0 && gs < Sq) {
            kv = Kg[(size_t)gs * Dq + c];
            vv = Vg[(size_t)gs * Dq + c];
        } else {
            kv = bk[h * DHq + c];
            vv = bv[h * DHq + c];
        }
        Ks[c * ATT_LD + r] = kv;
        Vs[c * ATT_LD + r] = vv;
    }
    __syncthreads();

    const int si = tid;
    const int s  = s0 + si;
    const float* qrow = g_Q + ((size_t)b * Sq + s) * Dq + h * DHq;

    float sc[5] = {0.f, 0.f, 0.f, 0.f, 0.f};
    #pragma unroll
    for (int d4 = 0; d4 < DHq; d4 += 4) {
        float4 q4 = *(const float4*)(qrow + d4);
        #pragma unroll
        for (int i = 0; i < 5; i++) {
            sc[i] += q4.x * Ks[(d4 + 0) * ATT_LD + si + i]
                   + q4.y * Ks[(d4 + 1) * ATT_LD + si + i]
                   + q4.z * Ks[(d4 + 2) * ATT_LD + si + i]
                   + q4.w * Ks[(d4 + 3) * ATT_LD + si + i];
        }
    }

    const float scale = 0.125f;  // 1/sqrt(64)
    float mx = sc[0];
    #pragma unroll
    for (int i = 1; i < 5; i++) mx = fmaxf(mx, sc[i]);
    float p[5], sum = 0.f;
    #pragma unroll
    for (int i = 0; i < 5; i++) {
        p[i] = __expf((sc[i] - mx) * scale);
        sum += p[i];
    }
    const float inv = 1.f / sum;
    #pragma unroll
    for (int i = 0; i < 5; i++) p[i] *= inv;

    float* orow = g_att + ((size_t)b * Sq + s) * Dq + h * DHq;
    #pragma unroll
    for (int d4 = 0; d4 < DHq; d4 += 4) {
        float4 o;
        o.x = 0.f; o.y = 0.f; o.z = 0.f; o.w = 0.f;
        #pragma unroll
        for (int i = 0; i < 5; i++) {
            const float pi = p[i];
            o.x += pi * Vs[(d4 + 0) * ATT_LD + si + i];
            o.y += pi * Vs[(d4 + 1) * ATT_LD + si + i];
            o.z += pi * Vs[(d4 + 2) * ATT_LD + si + i];
            o.w += pi * Vs[(d4 + 3) * ATT_LD + si + i];
        }
        *(float4*)(orow + d4) = o;
    }
}

// ---------------------------------------------------------------------------
// LayerNorm over last dim (768), population variance, eps inside sqrt.
// ---------------------------------------------------------------------------
__global__ void __launch_bounds__(256) ln_kernel(
    const float* __restrict__ gamma, const float* __restrict__ beta,
    float* __restrict__ outp)
{
    const int row = blockIdx.x;
    const float* y = g_Y + (size_t)row * Dq;
    const int tid = threadIdx.x;

    float v[3];
    float s = 0.f, ss = 0.f;
    #pragma unroll
    for (int j = 0; j < 3; j++) {
        v[j] = y[tid + j * 256];
        s  += v[j];
        ss += v[j] * v[j];
    }
    #pragma unroll
    for (int o = 16; o > 0; o >>= 1) {
        s  += __shfl_xor_sync(0xFFFFFFFFu, s,  o);
        ss += __shfl_xor_sync(0xFFFFFFFFu, ss, o);
    }
    __shared__ float rs[8], rss[8];
    const int w = tid >> 5;
    if ((tid & 31) == 0) { rs[w] = s; rss[w] = ss; }
    __syncthreads();
    s = 0.f; ss = 0.f;
    #pragma unroll
    for (int i = 0; i < 8; i++) { s += rs[i]; ss += rss[i]; }

    const float mu   = s * (1.f / 768.f);
    const float var  = ss * (1.f / 768.f) - mu * mu;
    const float rstd = rsqrtf(var + 1e-5f);

    #pragma unroll
    for (int j = 0; j < 3; j++) {
        const int c = tid + j * 256;
        outp[(size_t)row * Dq + c] = (v[j] - mu) * rstd * gamma[c] + beta[c];
    }
}

// ---------------------------------------------------------------------------
// Launch
// ---------------------------------------------------------------------------
extern "C" void kernel_launch(void* const* d_in, const int* in_sizes, int n_in,
                              void* d_out, int out_size)
{
    const float* x     = (const float*)d_in[0];
    const float* Wq    = (const float*)d_in[1];
    const float* bq    = (const float*)d_in[2];
    const float* Wk    = (const float*)d_in[3];
    const float* bk    = (const float*)d_in[4];
    const float* Wv    = (const float*)d_in[5];
    const float* bv    = (const float*)d_in[6];
    const float* Wo    = (const float*)d_in[7];
    const float* bo    = (const float*)d_in[8];
    const float* gamma = (const float*)d_in[9];
    const float* beta  = (const float*)d_in[10];
    float* out = (float*)d_out;

    // 1) QKV projections: [32768 x 2304] = x @ [Wq|Wk|Wv] + biases
    qkv_gemm_kernel<<<dim3(18, 256), 256>>>(x, Wq, bq, Wk, bk, Wv, bv);

    // 2) Banded local attention (kernel=5), halo taps use bk/bv
    const int att_smem = 2 * DHq * ATT_LD * (int)sizeof(float);  // 68,096 B
    cudaFuncSetAttribute(attn_kernel,
                         cudaFuncAttributeMaxDynamicSharedMemorySize, att_smem);
    attn_kernel<<<dim3(Sq / ATT_TS, Bq * Hq), 128, att_smem>>>(bk, bv);

    // 3) Output projection + bias + residual -> g_Y
    out_gemm_kernel<<<dim3(6, 256), 256>>>(x, Wo, bo);

    // 4) LayerNorm -> d_out
    ln_kernel<<<Mq, 256>>>(gamma, beta, out);
}

// round 3
// speedup vs baseline: 1.8776x; 1.8776x over previous
#include <cuda_runtime.h>
#include <cuda_fp16.h>
#include <cstdint>

// Problem constants
#define Bq 8
#define Sq 4096
#define Dq 768
#define Hq 12
#define DHq 64
#define Mq (Bq * Sq)          // 32768 rows

// GEMM tiling (mma.sync m16n8k16, fp16 in / fp32 acc)
#define BM 128
#define BN 128
#define BK 32
#define KSEG 24               // 768/32 chunks per segment
#define NCHUNK 72             // 3 segments x 24
#define ROWH 40               // smem row stride in halves (80B, conflict-free ldmatrix)
#define STAGE_B 20480         // (128*40 A + 128*40 B) * 2 bytes
#define NSTAGE 3
#define GEMM_SMEM (NSTAGE * STAGE_B)

// ---------------------------------------------------------------------------
// Scratch (device globals: allocation-free per harness rules)
// ---------------------------------------------------------------------------
__device__ float g_Q[(size_t)Mq * Dq];
__device__ float g_K[(size_t)Mq * Dq];
__device__ float g_V[(size_t)Mq * Dq];
__device__ float g_Y[(size_t)Mq * Dq];
__device__ __half g_xH[(size_t)Mq * Dq];
__device__ __half g_xL[(size_t)Mq * Dq];
__device__ __half g_attH[(size_t)Mq * Dq];
__device__ __half g_attL[(size_t)Mq * Dq];
__device__ __half g_WH[(size_t)4 * Dq * Dq];  // transposed [n][k]; rows: Wq|Wk|Wv|Wo
__device__ __half g_WL[(size_t)4 * Dq * Dq];

// ---------------------------------------------------------------------------
// PTX helpers
// ---------------------------------------------------------------------------
__device__ __forceinline__ uint32_t smem_u32(const void* p) {
    uint32_t a;
    asm("{ .reg .u64 t; cvta.to.shared.u64 t, %1; cvt.u32.u64 %0, t; }" : "=r"(a) : "l"(p));
    return a;
}
__device__ __forceinline__ void cp16(uint32_t dst, const void* src) {
    asm volatile("cp.async.cg.shared.global [%0], [%1], 16;" :: "r"(dst), "l"(src) : "memory");
}
__device__ __forceinline__ void cp_commit() { asm volatile("cp.async.commit_group;" ::: "memory"); }
__device__ __forceinline__ void cp_wait1()  { asm volatile("cp.async.wait_group 1;" ::: "memory"); }

__device__ __forceinline__ void ldsm_x4(uint32_t (&r)[4], uint32_t addr) {
    asm volatile("ldmatrix.sync.aligned.m8n8.x4.shared.b16 {%0,%1,%2,%3}, [%4];"
                 : "=r"(r[0]), "=r"(r[1]), "=r"(r[2]), "=r"(r[3]) : "r"(addr));
}
__device__ __forceinline__ void mma16816(float (&d)[4], const uint32_t (&a)[4],
                                         uint32_t b0, uint32_t b1) {
    asm volatile("mma.sync.aligned.m16n8k16.row.col.f32.f16.f16.f32 "
                 "{%0,%1,%2,%3}, {%4,%5,%6,%7}, {%8,%9}, {%0,%1,%2,%3};"
                 : "+f"(d[0]), "+f"(d[1]), "+f"(d[2]), "+f"(d[3])
                 : "r"(a[0]), "r"(a[1]), "r"(a[2]), "r"(a[3]), "r"(b0), "r"(b1));
}
__device__ __forceinline__ void split_h(float v, __half& h, __half& l) {
    h = __float2half_rn(v);
    l = __float2half_rn(v - __half2float(h));
}

// ---------------------------------------------------------------------------
// Conversion: x -> hi/lo fp16
// ---------------------------------------------------------------------------
__global__ void __launch_bounds__(256) conv_x_kernel(const float* __restrict__ x) {
    const size_t i = ((size_t)blockIdx.x * 256 + threadIdx.x) * 4;
    float4 v = *(const float4*)(x + i);
    __half h0, l0, h1, l1, h2, l2, h3, l3;
    split_h(v.x, h0, l0); split_h(v.y, h1, l1);
    split_h(v.z, h2, l2); split_h(v.w, h3, l3);
    *(__half2*)(g_xH + i)     = __halves2half2(h0, h1);
    *(__half2*)(g_xH + i + 2) = __halves2half2(h2, h3);
    *(__half2*)(g_xL + i)     = __halves2half2(l0, l1);
    *(__half2*)(g_xL + i + 2) = __halves2half2(l2, l3);
}

// ---------------------------------------------------------------------------
// Conversion: weights -> transposed [n][k] hi/lo fp16
// ---------------------------------------------------------------------------
__global__ void __launch_bounds__(256) conv_w_kernel(
    const float* __restrict__ Wq, const float* __restrict__ Wk,
    const float* __restrict__ Wv, const float* __restrict__ Wo)
{
    __shared__ float t[32][33];
    const int z = blockIdx.z;
    const float* W = (z == 0) ? Wq : (z == 1) ? Wk : (z == 2) ? Wv : Wo;
    const int rowoff = z * Dq;
    const int n0 = blockIdx.x * 32, k0 = blockIdx.y * 32;
    const int tx = threadIdx.x & 31, ty = threadIdx.x >> 5;

    #pragma unroll
    for (int i = 0; i < 4; i++)
        t[ty + i * 8][tx] = W[(size_t)(k0 + ty + i * 8) * Dq + n0 + tx];
    __syncthreads();
    #pragma unroll
    for (int i = 0; i < 4; i++) {
        const int n = n0 + ty + i * 8;
        const float w = t[tx][ty + i * 8];   // = W[k0+tx][n]
        __half h, l;
        split_h(w, h, l);
        const size_t o = (size_t)(rowoff + n) * Dq + k0 + tx;
        g_WH[o] = h;
        g_WL[o] = l;
    }
}

// ---------------------------------------------------------------------------
// Tensor-core GEMM via mma.sync: C[BM x BN] = A @ W^T, hi/lo 3-product split
// folded into K' = 3*768: seg0 Ah*Bh, seg1 Al*Bh, seg2 Ah*Bl.
// mode 0: A = x (hi/lo), outputs Q|K|V (+bias), grid (18, 256)
// mode 1: A = att (hi/lo), g_Y = C + bo + x, grid (6, 256)
// ---------------------------------------------------------------------------
__global__ void __launch_bounds__(256, 2) tc_gemm_kernel(
    const __half* __restrict__ AHp, const __half* __restrict__ ALp,
    const float* __restrict__ bias_a, const float* __restrict__ bias_b,
    const float* __restrict__ bias_c, const float* __restrict__ resid,
    int wrow_base, int mode)
{
    extern __shared__ __align__(128) char smem_raw[];
    const uint32_t base = smem_u32(smem_raw);

    const int tid  = threadIdx.x;
    const int wid  = tid >> 5;
    const int lane = tid & 31;
    const int m0 = blockIdx.y * BM;
    const int bx = blockIdx.x;
    const int nrow0 = wrow_base + bx * BN;   // weight row block in g_WH/g_WL

    const int wm0 = (wid & 3) * 32;          // warp M offset (4 warps in M)
    const int wn0 = (wid >> 2) * 64;         // warp N offset (2 warps in N)

    // per-thread load indices (2 x 16B per tile per stage)
    const int lrow0 = tid >> 2,  lsg0 = (tid & 3);
    const int lrow1 = (tid + 256) >> 2, lsg1 = (tid & 3);

    auto load_stage = [&](int c, int s) {
        const int seg = c / KSEG;
        const __half* Ap = (seg == 1) ? ALp : AHp;
        const __half* Bp = (seg == 2) ? g_WL : g_WH;
        const int kk0 = (c % KSEG) * BK;
        const uint32_t sa = base + (uint32_t)s * STAGE_B;
        const uint32_t sb = sa + (BM * ROWH * 2);
        cp16(sa + (lrow0 * ROWH + lsg0 * 8) * 2, Ap + (size_t)(m0 + lrow0) * Dq + kk0 + lsg0 * 8);
        cp16(sa + (lrow1 * ROWH + lsg1 * 8) * 2, Ap + (size_t)(m0 + lrow1) * Dq + kk0 + lsg1 * 8);
        cp16(sb + (lrow0 * ROWH + lsg0 * 8) * 2, Bp + (size_t)(nrow0 + lrow0) * Dq + kk0 + lsg0 * 8);
        cp16(sb + (lrow1 * ROWH + lsg1 * 8) * 2, Bp + (size_t)(nrow0 + lrow1) * Dq + kk0 + lsg1 * 8);
        cp_commit();
    };

    float acc[2][8][4];
    #pragma unroll
    for (int mi = 0; mi < 2; mi++)
        #pragma unroll
        for (int n8 = 0; n8 < 8; n8++)
            #pragma unroll
            for (int j = 0; j < 4; j++) acc[mi][n8][j] = 0.f;

    // ldmatrix lane addressing (constant per thread)
    const int a_r = (lane & 7) + ((lane >> 3) & 1) * 8;   // row within m16 tile
    const int a_c = ((lane >> 4) & 1) * 8;                // col within k16
    const int b_r = (lane & 7) + ((lane >> 4) & 1) * 8;   // row within n16 group
    const int b_c = ((lane >> 3) & 1) * 8;

    load_stage(0, 0);
    load_stage(1, 1);

    for (int c = 0; c < NCHUNK; c++) {
        cp_wait1();
        __syncthreads();
        if (c + 2 < NCHUNK) load_stage(c + 2, (c + 2) % NSTAGE);

        const uint32_t sa = base + (uint32_t)(c % NSTAGE) * STAGE_B;
        const uint32_t sb = sa + (BM * ROWH * 2);

        #pragma unroll
        for (int ks = 0; ks < 2; ks++) {
            uint32_t a[2][4];
            #pragma unroll
            for (int mi = 0; mi < 2; mi++) {
                const int row = wm0 + mi * 16 + a_r;
                const int col = ks * 16 + a_c;
                ldsm_x4(a[mi], sa + (uint32_t)(row * ROWH + col) * 2);
            }
            #pragma unroll
            for (int g = 0; g < 4; g++) {
                uint32_t b[4];
                const int row = wn0 + g * 16 + b_r;
                const int col = ks * 16 + b_c;
                ldsm_x4(b, sb + (uint32_t)(row * ROWH + col) * 2);
                #pragma unroll
                for (int mi = 0; mi < 2; mi++) {
                    mma16816(acc[mi][g * 2 + 0], a[mi], b[0], b[1]);
                    mma16816(acc[mi][g * 2 + 1], a[mi], b[2], b[3]);
                }
            }
        }
    }

    // ---- epilogue ----
    float* outp;
    const float* bias;
    int n0in;
    if (mode == 0) {
        const int sel = bx / 6;
        n0in = (bx % 6) * BN;
        outp = (sel == 0) ? g_Q : (sel == 1) ? g_K : g_V;
        bias = (sel == 0) ? bias_a : (sel == 1) ? bias_b : bias_c;
    } else {
        n0in = bx * BN;
        outp = g_Y;
        bias = bias_a;
    }

    const int qr = lane >> 2;
    const int qc = (lane & 3) * 2;
    #pragma unroll
    for (int mi = 0; mi < 2; mi++) {
        #pragma unroll
        for (int n8 = 0; n8 < 8; n8++) {
            const int n = n0in + wn0 + n8 * 8 + qc;
            const float b0 = bias[n], b1 = bias[n + 1];
            #pragma unroll
            for (int half = 0; half < 2; half++) {
                const int m = m0 + wm0 + mi * 16 + qr + half * 8;
                const size_t o = (size_t)m * Dq + n;
                float2 v;
                v.x = acc[mi][n8][half * 2 + 0] + b0;
                v.y = acc[mi][n8][half * 2 + 1] + b1;
                if (mode == 1) {
                    v.x += resid[o];
                    v.y += resid[o + 1];
                }
                *(float2*)(outp + o) = v;
            }
        }
    }
}

// ---------------------------------------------------------------------------
// Banded attention (kernel=5). Reads fp32 Q/K/V, writes att as hi/lo fp16.
// ---------------------------------------------------------------------------
#define ATT_TS 128
#define ATT_LD 133

__global__ void __launch_bounds__(128) attn_kernel(
    const float* __restrict__ bk, const float* __restrict__ bv)
{
    extern __shared__ float sm[];
    float* Ks = sm;
    float* Vs = sm + DHq * ATT_LD;

    const int bh = blockIdx.y;
    const int b  = bh / Hq;
    const int h  = bh % Hq;
    const int s0 = blockIdx.x * ATT_TS;

    const size_t basep = ((size_t)b * Sq) * Dq + h * DHq;
    const float* Kg = g_K + basep;
    const float* Vg = g_V + basep;

    const int tid = threadIdx.x;
    for (int idx = tid; idx < (ATT_TS + 4) * DHq; idx += 128) {
        const int r = idx >> 6;
        const int c = idx & 63;
        const int gs = s0 - 2 + r;
        float kv, vv;
        if (gs >= 0 && gs < Sq) {
            kv = Kg[(size_t)gs * Dq + c];
            vv = Vg[(size_t)gs * Dq + c];
        } else {
            kv = bk[h * DHq + c];
            vv = bv[h * DHq + c];
        }
        Ks[c * ATT_LD + r] = kv;
        Vs[c * ATT_LD + r] = vv;
    }
    __syncthreads();

    const int si = tid;
    const int s  = s0 + si;
    const float* qrow = g_Q + ((size_t)b * Sq + s) * Dq + h * DHq;

    float sc[5] = {0.f, 0.f, 0.f, 0.f, 0.f};
    #pragma unroll
    for (int d4 = 0; d4 < DHq; d4 += 4) {
        float4 q4 = *(const float4*)(qrow + d4);
        #pragma unroll
        for (int i = 0; i < 5; i++) {
            sc[i] += q4.x * Ks[(d4 + 0) * ATT_LD + si + i]
                   + q4.y * Ks[(d4 + 1) * ATT_LD + si + i]
                   + q4.z * Ks[(d4 + 2) * ATT_LD + si + i]
                   + q4.w * Ks[(d4 + 3) * ATT_LD + si + i];
        }
    }

    float mx = sc[0];
    #pragma unroll
    for (int i = 1; i < 5; i++) mx = fmaxf(mx, sc[i]);
    float p[5], sum = 0.f;
    #pragma unroll
    for (int i = 0; i < 5; i++) {
        p[i] = __expf((sc[i] - mx) * 0.125f);
        sum += p[i];
    }
    const float inv = 1.f / sum;
    #pragma unroll
    for (int i = 0; i < 5; i++) p[i] *= inv;

    const size_t obase = ((size_t)b * Sq + s) * Dq + h * DHq;
    #pragma unroll
    for (int d4 = 0; d4 < DHq; d4 += 4) {
        float o[4] = {0.f, 0.f, 0.f, 0.f};
        #pragma unroll
        for (int i = 0; i < 5; i++) {
            const float pi = p[i];
            o[0] += pi * Vs[(d4 + 0) * ATT_LD + si + i];
            o[1] += pi * Vs[(d4 + 1) * ATT_LD + si + i];
            o[2] += pi * Vs[(d4 + 2) * ATT_LD + si + i];
            o[3] += pi * Vs[(d4 + 3) * ATT_LD + si + i];
        }
        __half h0, l0, h1, l1, h2, l2, h3, l3;
        split_h(o[0], h0, l0); split_h(o[1], h1, l1);
        split_h(o[2], h2, l2); split_h(o[3], h3, l3);
        *(__half2*)(g_attH + obase + d4)     = __halves2half2(h0, h1);
        *(__half2*)(g_attH + obase + d4 + 2) = __halves2half2(h2, h3);
        *(__half2*)(g_attL + obase + d4)     = __halves2half2(l0, l1);
        *(__half2*)(g_attL + obase + d4 + 2) = __halves2half2(l2, l3);
    }
}

// ---------------------------------------------------------------------------
// LayerNorm over last dim (768)
// ---------------------------------------------------------------------------
__global__ void __launch_bounds__(256) ln_kernel(
    const float* __restrict__ gamma, const float* __restrict__ beta,
    float* __restrict__ outp)
{
    const int row = blockIdx.x;
    const float* y = g_Y + (size_t)row * Dq;
    const int tid = threadIdx.x;

    float v[3];
    float s = 0.f, ss = 0.f;
    #pragma unroll
    for (int j = 0; j < 3; j++) {
        v[j] = y[tid + j * 256];
        s  += v[j];
        ss += v[j] * v[j];
    }
    #pragma unroll
    for (int o = 16; o > 0; o >>= 1) {
        s  += __shfl_xor_sync(0xFFFFFFFFu, s,  o);
        ss += __shfl_xor_sync(0xFFFFFFFFu, ss, o);
    }
    __shared__ float rs[8], rss[8];
    const int w = tid >> 5;
    if ((tid & 31) == 0) { rs[w] = s; rss[w] = ss; }
    __syncthreads();
    s = 0.f; ss = 0.f;
    #pragma unroll
    for (int i = 0; i < 8; i++) { s += rs[i]; ss += rss[i]; }

    const float mu   = s * (1.f / 768.f);
    const float var  = ss * (1.f / 768.f) - mu * mu;
    const float rstd = rsqrtf(var + 1e-5f);

    #pragma unroll
    for (int j = 0; j < 3; j++) {
        const int c = tid + j * 256;
        outp[(size_t)row * Dq + c] = (v[j] - mu) * rstd * gamma[c] + beta[c];
    }
}

// ---------------------------------------------------------------------------
// Launch
// ---------------------------------------------------------------------------
extern "C" void kernel_launch(void* const* d_in, const int* in_sizes, int n_in,
                              void* d_out, int out_size)
{
    const float* x     = (const float*)d_in[0];
    const float* Wq    = (const float*)d_in[1];
    const float* bq    = (const float*)d_in[2];
    const float* Wk    = (const float*)d_in[3];
    const float* bk    = (const float*)d_in[4];
    const float* Wv    = (const float*)d_in[5];
    const float* bv    = (const float*)d_in[6];
    const float* Wo    = (const float*)d_in[7];
    const float* bo    = (const float*)d_in[8];
    const float* gamma = (const float*)d_in[9];
    const float* beta  = (const float*)d_in[10];
    float* out = (float*)d_out;

    static int configured = 0;
    if (!configured) {
        cudaFuncSetAttribute(tc_gemm_kernel,
                             cudaFuncAttributeMaxDynamicSharedMemorySize, GEMM_SMEM);
        cudaFuncSetAttribute(attn_kernel,
                             cudaFuncAttributeMaxDynamicSharedMemorySize,
                             2 * DHq * ATT_LD * (int)sizeof(float));
        configured = 1;
    }

    __half *xH, *xL, *attH, *attL;
    cudaGetSymbolAddress((void**)&xH, g_xH);
    cudaGetSymbolAddress((void**)&xL, g_xL);
    cudaGetSymbolAddress((void**)&attH, g_attH);
    cudaGetSymbolAddress((void**)&attL, g_attL);

    // 0) split x and weights into fp16 hi/lo (weights transposed)
    conv_x_kernel<<<(Mq * Dq) / 1024, 256>>>(x);
    conv_w_kernel<<<dim3(24, 24, 4), 256>>>(Wq, Wk, Wv, Wo);

    // 1) QKV projections (N=2304 in 18 tiles of 128)
    tc_gemm_kernel<<<dim3(18, Mq / BM), 256, GEMM_SMEM>>>(
        xH, xL, bq, bk, bv, nullptr, 0, 0);

    // 2) Banded local attention -> att hi/lo fp16
    attn_kernel<<<dim3(Sq / ATT_TS, Bq * Hq), 128,
                  2 * DHq * ATT_LD * (int)sizeof(float)>>>(bk, bv);

    // 3) Output projection + bias + residual -> g_Y
    tc_gemm_kernel<<<dim3(6, Mq / BM), 256, GEMM_SMEM>>>(
        attH, attL, bo, nullptr, nullptr, x, 3 * Dq, 1);

    // 4) LayerNorm -> d_out
    ln_kernel<<<Mq, 256>>>(gamma, beta, out);
}

// round 4
// speedup vs baseline: 2.9712x; 1.5824x over previous
#include <cuda_runtime.h>
#include <cuda_fp16.h>
#include <cstdint>

// Problem constants
#define Bq 8
#define Sq 4096
#define Dq 768
#define Hq 12
#define DHq 64
#define Mq (Bq * Sq)          // 32768 rows

// int8 GEMM tiling (mma.sync m16n8k32 s8 -> s32)
#define BM 128
#define BN 128
#define BK 64                 // int8 K elements per chunk
#define NCHUNK 12             // 768/64
#define ROWB 80               // smem row stride bytes (64 + 16 pad)
#define MAT_B (128 * ROWB)    // 10240 bytes per matrix tile
#define STAGE_B (4 * MAT_B)   // A0,A1,B0,B1 = 40960
#define NSTAGE 3
#define GEMM_SMEM (NSTAGE * STAGE_B)   // 122880

#define QMAX 16256.0f         // 127*128

// ---------------------------------------------------------------------------
// Scratch (device globals)
// ---------------------------------------------------------------------------
__device__ float g_Q[(size_t)Mq * Dq];
__device__ float g_K[(size_t)Mq * Dq];
__device__ float g_V[(size_t)Mq * Dq];
__device__ float g_att[(size_t)Mq * Dq];
__device__ float g_Y[(size_t)Mq * Dq];
__device__ int8_t g_xq0[(size_t)Mq * Dq];
__device__ int8_t g_xq1[(size_t)Mq * Dq];
__device__ float  g_xsc[Mq];
__device__ int8_t g_aq0[(size_t)Mq * Dq];
__device__ int8_t g_aq1[(size_t)Mq * Dq];
__device__ float  g_asc[Mq];
__device__ int8_t g_wq0[(size_t)4 * Dq * Dq];   // transposed [n][k]; rows: Wq|Wk|Wv|Wo
__device__ int8_t g_wq1[(size_t)4 * Dq * Dq];
__device__ float  g_wsc[4 * Dq];
__device__ unsigned int g_wmax[4 * Dq];

// ---------------------------------------------------------------------------
// PTX helpers
// ---------------------------------------------------------------------------
__device__ __forceinline__ uint32_t smem_u32(const void* p) {
    uint32_t a;
    asm("{ .reg .u64 t; cvta.to.shared.u64 t, %1; cvt.u32.u64 %0, t; }" : "=r"(a) : "l"(p));
    return a;
}
__device__ __forceinline__ void cp16(uint32_t dst, const void* src) {
    asm volatile("cp.async.cg.shared.global [%0], [%1], 16;" :: "r"(dst), "l"(src) : "memory");
}
__device__ __forceinline__ void cp_commit() { asm volatile("cp.async.commit_group;" ::: "memory"); }
__device__ __forceinline__ void cp_wait1()  { asm volatile("cp.async.wait_group 1;" ::: "memory"); }

__device__ __forceinline__ void ldsm_x4(uint32_t (&r)[4], uint32_t addr) {
    asm volatile("ldmatrix.sync.aligned.m8n8.x4.shared.b16 {%0,%1,%2,%3}, [%4];"
                 : "=r"(r[0]), "=r"(r[1]), "=r"(r[2]), "=r"(r[3]) : "r"(addr));
}
// D += A(s8 m16k32) * B(s8 n8k32), s32 accumulate
__device__ __forceinline__ void imma(int (&d)[4], const uint32_t (&a)[4],
                                     uint32_t b0, uint32_t b1) {
    asm volatile("mma.sync.aligned.m16n8k32.row.col.s32.s8.s8.s32 "
                 "{%0,%1,%2,%3}, {%4,%5,%6,%7}, {%8,%9}, {%0,%1,%2,%3};"
                 : "+r"(d[0]), "+r"(d[1]), "+r"(d[2]), "+r"(d[3])
                 : "r"(a[0]), "r"(a[1]), "r"(a[2]), "r"(a[3]), "r"(b0), "r"(b1));
}

// ---------------------------------------------------------------------------
// Row quantizer: per-row absmax -> 2-digit int8 (A0*128 + A1)
// ---------------------------------------------------------------------------
__global__ void __launch_bounds__(256) quant_rows_kernel(
    const float* __restrict__ src, int8_t* __restrict__ q0,
    int8_t* __restrict__ q1, float* __restrict__ scl)
{
    const int row = blockIdx.x;
    const int tid = threadIdx.x;
    const float* s = src + (size_t)row * Dq;

    float v[3], mx = 0.f;
    #pragma unroll
    for (int j = 0; j < 3; j++) {
        v[j] = s[tid + j * 256];
        mx = fmaxf(mx, fabsf(v[j]));
    }
    #pragma unroll
    for (int o = 16; o > 0; o >>= 1)
        mx = fmaxf(mx, __shfl_xor_sync(0xFFFFFFFFu, mx, o));
    __shared__ float rm[8];
    if ((tid & 31) == 0) rm[tid >> 5] = mx;
    __syncthreads();
    mx = fmaxf(fmaxf(fmaxf(rm[0], rm[1]), fmaxf(rm[2], rm[3])),
               fmaxf(fmaxf(rm[4], rm[5]), fmaxf(rm[6], rm[7])));

    const float inv = (mx > 0.f) ? (QMAX / mx) : 0.f;
    if (tid == 0) scl[row] = (mx > 0.f) ? (mx / QMAX) : 0.f;

    #pragma unroll
    for (int j = 0; j < 3; j++) {
        const int c = tid + j * 256;
        const int n = __float2int_rn(v[j] * inv);
        const int a0 = (n + 64) >> 7;
        const int a1 = n - (a0 << 7);
        q0[(size_t)row * Dq + c] = (int8_t)a0;
        q1[(size_t)row * Dq + c] = (int8_t)a1;
    }
}

// ---------------------------------------------------------------------------
// Weight absmax per output column (atomicMax on positive float bits)
// ---------------------------------------------------------------------------
__global__ void __launch_bounds__(256) wmax_zero_kernel() {
    const int i = blockIdx.x * 256 + threadIdx.x;
    if (i < 4 * Dq) g_wmax[i] = 0u;
}
__global__ void __launch_bounds__(256) wmax_kernel(
    const float* __restrict__ Wq, const float* __restrict__ Wk,
    const float* __restrict__ Wv, const float* __restrict__ Wo)
{
    const int w = blockIdx.z;
    const float* W = (w == 0) ? Wq : (w == 1) ? Wk : (w == 2) ? Wv : Wo;
    const int n = blockIdx.x * 256 + threadIdx.x;   // 3 blocks x 256 = 768
    const int k0 = blockIdx.y * 96;                 // 8 chunks of 96
    float mx = 0.f;
    for (int j = 0; j < 96; j++)
        mx = fmaxf(mx, fabsf(W[(size_t)(k0 + j) * Dq + n]));
    atomicMax(&g_wmax[w * Dq + n], __float_as_uint(mx));
}

// ---------------------------------------------------------------------------
// Weight quantize + transpose: out[n][k] digits
// ---------------------------------------------------------------------------
__global__ void __launch_bounds__(256) wquant_kernel(
    const float* __restrict__ Wq, const float* __restrict__ Wk,
    const float* __restrict__ Wv, const float* __restrict__ Wo)
{
    __shared__ float t[32][33];
    const int w = blockIdx.z;
    const float* W = (w == 0) ? Wq : (w == 1) ? Wk : (w == 2) ? Wv : Wo;
    const int n0 = blockIdx.x * 32, k0 = blockIdx.y * 32;
    const int tx = threadIdx.x & 31, ty = threadIdx.x >> 5;

    #pragma unroll
    for (int i = 0; i < 4; i++)
        t[ty + i * 8][tx] = W[(size_t)(k0 + ty + i * 8) * Dq + n0 + tx];
    __syncthreads();
    #pragma unroll
    for (int i = 0; i < 4; i++) {
        const int n = n0 + ty + i * 8;
        const float mx = __uint_as_float(g_wmax[w * Dq + n]);
        const float inv = (mx > 0.f) ? (QMAX / mx) : 0.f;
        if (k0 == 0 && tx == 0)
            g_wsc[w * Dq + n] = (mx > 0.f) ? (mx / QMAX) : 0.f;
        const float val = t[tx][ty + i * 8];        // W[k0+tx][n]
        const int q = __float2int_rn(val * inv);
        const int a0 = (q + 64) >> 7;
        const int a1 = q - (a0 << 7);
        const size_t o = (size_t)(w * Dq + n) * Dq + k0 + tx;
        g_wq0[o] = (int8_t)a0;
        g_wq1[o] = (int8_t)a1;
    }
}

// ---------------------------------------------------------------------------
// int8 tensor-core GEMM: C = A @ W^T, 2-digit emulation, 3 products.
// mode 0: outputs Q|K|V (+bias), grid (18, 256)
// mode 1: g_Y = C + bo + resid, grid (6, 256)
// ---------------------------------------------------------------------------
__global__ void __launch_bounds__(256, 1) ig_gemm_kernel(
    const int8_t* __restrict__ Aq0, const int8_t* __restrict__ Aq1,
    const float* __restrict__ Asc,
    const float* __restrict__ bias_a, const float* __restrict__ bias_b,
    const float* __restrict__ bias_c, const float* __restrict__ resid,
    int wbase, int mode)
{
    extern __shared__ __align__(128) char smem_raw[];
    const uint32_t base = smem_u32(smem_raw);

    const int tid  = threadIdx.x;
    const int wid  = tid >> 5;
    const int lane = tid & 31;
    const int m0 = blockIdx.y * BM;
    const int bx = blockIdx.x;
    const int nrow0 = wbase + bx * BN;

    const int wm0 = (wid & 3) * 32;          // 4 warps in M
    const int wn0 = (wid >> 2) * 64;         // 2 warps in N

    auto load_stage = [&](int c, int s) {
        const int k0 = c * BK;
        const uint32_t sb = base + (uint32_t)s * STAGE_B;
        #pragma unroll
        for (int half = 0; half < 2; half++) {
            const int u = tid + half * 256;          // 0..511
            const int row = u >> 2, seg = (u & 3) * 16;
            const uint32_t so = (uint32_t)(row * ROWB + seg);
            cp16(sb + 0 * MAT_B + so, Aq0 + (size_t)(m0 + row) * Dq + k0 + seg);
            cp16(sb + 1 * MAT_B + so, Aq1 + (size_t)(m0 + row) * Dq + k0 + seg);
            cp16(sb + 2 * MAT_B + so, g_wq0 + (size_t)(nrow0 + row) * Dq + k0 + seg);
            cp16(sb + 3 * MAT_B + so, g_wq1 + (size_t)(nrow0 + row) * Dq + k0 + seg);
        }
        cp_commit();
    };

    int hi[2][8][4], mid[2][8][4];
    #pragma unroll
    for (int mi = 0; mi < 2; mi++)
        #pragma unroll
        for (int n8 = 0; n8 < 8; n8++)
            #pragma unroll
            for (int j = 0; j < 4; j++) { hi[mi][n8][j] = 0; mid[mi][n8][j] = 0; }

    // ldmatrix lane addressing: tile j = lane>>3 supplies row (lane&7) of tile j
    const int lrow = (lane & 7) + ((lane >> 3) & 1) * 8;   // row within 16-row group
    const int lk16 = (lane >> 4) * 16;                     // k-halves

    load_stage(0, 0);
    load_stage(1, 1);

    for (int c = 0; c < NCHUNK; c++) {
        cp_wait1();
        __syncthreads();
        if (c + 2 < NCHUNK) load_stage(c + 2, (c + 2) % NSTAGE);

        const uint32_t sb = base + (uint32_t)(c % NSTAGE) * STAGE_B;
        const uint32_t sA0 = sb, sA1 = sb + MAT_B, sB0 = sb + 2 * MAT_B, sB1 = sb + 3 * MAT_B;

        #pragma unroll
        for (int ks = 0; ks < 2; ks++) {
            const uint32_t koff = (uint32_t)(ks * 32 + lk16);
            uint32_t a0[2][4], a1[2][4];
            #pragma unroll
            for (int mi = 0; mi < 2; mi++) {
                const uint32_t ro = (uint32_t)((wm0 + mi * 16 + lrow) * ROWB) + koff;
                ldsm_x4(a0[mi], sA0 + ro);
                ldsm_x4(a1[mi], sA1 + ro);
            }
            #pragma unroll
            for (int g = 0; g < 4; g++) {
                uint32_t b0[4], b1[4];
                const uint32_t ro = (uint32_t)((wn0 + g * 16 + lrow) * ROWB) + koff;
                ldsm_x4(b0, sB0 + ro);
                ldsm_x4(b1, sB1 + ro);
                #pragma unroll
                for (int mi = 0; mi < 2; mi++) {
                    imma(hi[mi][g * 2 + 0], a0[mi], b0[0], b0[2]);
                    imma(hi[mi][g * 2 + 1], a0[mi], b0[1], b0[3]);
                    imma(mid[mi][g * 2 + 0], a0[mi], b1[0], b1[2]);
                    imma(mid[mi][g * 2 + 1], a0[mi], b1[1], b1[3]);
                    imma(mid[mi][g * 2 + 0], a1[mi], b0[0], b0[2]);
                    imma(mid[mi][g * 2 + 1], a1[mi], b0[1], b0[3]);
                }
            }
        }
    }

    // ---- epilogue ----
    float* outp;
    const float* bias;
    int n0in;
    if (mode == 0) {
        const int sel = bx / 6;
        n0in = (bx % 6) * BN;
        outp = (sel == 0) ? g_Q : (sel == 1) ? g_K : g_V;
        bias = (sel == 0) ? bias_a : (sel == 1) ? bias_b : bias_c;
    } else {
        n0in = bx * BN;
        outp = g_Y;
        bias = bias_a;
    }

    const int qr = lane >> 2;
    const int qc = (lane & 3) * 2;
    #pragma unroll
    for (int mi = 0; mi < 2; mi++) {
        #pragma unroll
        for (int half = 0; half < 2; half++) {
            const int m = m0 + wm0 + mi * 16 + qr + half * 8;
            const float sa128 = Asc[m] * 128.f;
            #pragma unroll
            for (int n8 = 0; n8 < 8; n8++) {
                const int nl = wn0 + n8 * 8 + qc;
                const float sb0 = g_wsc[nrow0 + nl] * sa128;
                const float sb1 = g_wsc[nrow0 + nl + 1] * sa128;
                const int n = n0in + nl;
                const size_t o = (size_t)m * Dq + n;
                const int t0 = hi[mi][n8][half * 2 + 0] * 128 + mid[mi][n8][half * 2 + 0];
                const int t1 = hi[mi][n8][half * 2 + 1] * 128 + mid[mi][n8][half * 2 + 1];
                float2 v;
                v.x = (float)t0 * sb0 + bias[n];
                v.y = (float)t1 * sb1 + bias[n + 1];
                if (mode == 1) {
                    v.x += resid[o];
                    v.y += resid[o + 1];
                }
                *(float2*)(outp + o) = v;
            }
        }
    }
}

// ---------------------------------------------------------------------------
// Banded attention v2: 256-position tile, single smem buffer (K then V phase).
// ---------------------------------------------------------------------------
#define AT_TS 256
#define AT_HALO 260
#define AT_LD 261
#define ATT_SMEM (DHq * AT_LD * 4)   // 66,816 B

__global__ void __launch_bounds__(256) attn_kernel(
    const float* __restrict__ bk, const float* __restrict__ bv)
{
    extern __shared__ float sm[];

    const int by = blockIdx.y;
    const int b  = by / Hq;
    const int h  = by % Hq;
    const int s0 = blockIdx.x * AT_TS;

    const size_t basep = ((size_t)b * Sq) * Dq + h * DHq;
    const int tid = threadIdx.x;
    const int si = tid;
    const int s  = s0 + si;

    // ---- phase 1: K scores ----
    {
        const float* Kg = g_K + basep;
        for (int idx = tid; idx < AT_HALO * DHq; idx += 256) {
            const int r = idx >> 6;
            const int c = idx & 63;
            const int gs = s0 - 2 + r;
            sm[c * AT_LD + r] = (gs >= 0 && gs < Sq)
                                ? Kg[(size_t)gs * Dq + c] : bk[h * DHq + c];
        }
    }
    __syncthreads();

    const float* qrow = g_Q + ((size_t)b * Sq + s) * Dq + h * DHq;
    float sc[5] = {0.f, 0.f, 0.f, 0.f, 0.f};
    #pragma unroll
    for (int d4 = 0; d4 < DHq; d4 += 4) {
        float4 q4 = *(const float4*)(qrow + d4);
        #pragma unroll
        for (int i = 0; i < 5; i++) {
            sc[i] += q4.x * sm[(d4 + 0) * AT_LD + si + i]
                   + q4.y * sm[(d4 + 1) * AT_LD + si + i]
                   + q4.z * sm[(d4 + 2) * AT_LD + si + i]
                   + q4.w * sm[(d4 + 3) * AT_LD + si + i];
        }
    }

    float mx = sc[0];
    #pragma unroll
    for (int i = 1; i < 5; i++) mx = fmaxf(mx, sc[i]);
    float p[5], sum = 0.f;
    #pragma unroll
    for (int i = 0; i < 5; i++) {
        p[i] = __expf((sc[i] - mx) * 0.125f);
        sum += p[i];
    }
    const float inv = 1.f / sum;
    #pragma unroll
    for (int i = 0; i < 5; i++) p[i] *= inv;

    // ---- phase 2: V aggregate (reuse smem) ----
    __syncthreads();
    {
        const float* Vg = g_V + basep;
        for (int idx = tid; idx < AT_HALO * DHq; idx += 256) {
            const int r = idx >> 6;
            const int c = idx & 63;
            const int gs = s0 - 2 + r;
            sm[c * AT_LD + r] = (gs >= 0 && gs < Sq)
                                ? Vg[(size_t)gs * Dq + c] : bv[h * DHq + c];
        }
    }
    __syncthreads();

    float* orow = g_att + ((size_t)b * Sq + s) * Dq + h * DHq;
    #pragma unroll
    for (int d4 = 0; d4 < DHq; d4 += 4) {
        float4 o = {0.f, 0.f, 0.f, 0.f};
        #pragma unroll
        for (int i = 0; i < 5; i++) {
            const float pi = p[i];
            o.x += pi * sm[(d4 + 0) * AT_LD + si + i];
            o.y += pi * sm[(d4 + 1) * AT_LD + si + i];
            o.z += pi * sm[(d4 + 2) * AT_LD + si + i];
            o.w += pi * sm[(d4 + 3) * AT_LD + si + i];
        }
        *(float4*)(orow + d4) = o;
    }
}

// ---------------------------------------------------------------------------
// LayerNorm over last dim (768)
// ---------------------------------------------------------------------------
__global__ void __launch_bounds__(256) ln_kernel(
    const float* __restrict__ gamma, const float* __restrict__ beta,
    float* __restrict__ outp)
{
    const int row = blockIdx.x;
    const float* y = g_Y + (size_t)row * Dq;
    const int tid = threadIdx.x;

    float v[3];
    float s = 0.f, ss = 0.f;
    #pragma unroll
    for (int j = 0; j < 3; j++) {
        v[j] = y[tid + j * 256];
        s  += v[j];
        ss += v[j] * v[j];
    }
    #pragma unroll
    for (int o = 16; o > 0; o >>= 1) {
        s  += __shfl_xor_sync(0xFFFFFFFFu, s,  o);
        ss += __shfl_xor_sync(0xFFFFFFFFu, ss, o);
    }
    __shared__ float rs[8], rss[8];
    const int w = tid >> 5;
    if ((tid & 31) == 0) { rs[w] = s; rss[w] = ss; }
    __syncthreads();
    s = 0.f; ss = 0.f;
    #pragma unroll
    for (int i = 0; i < 8; i++) { s += rs[i]; ss += rss[i]; }

    const float mu   = s * (1.f / 768.f);
    const float var  = ss * (1.f / 768.f) - mu * mu;
    const float rstd = rsqrtf(var + 1e-5f);

    #pragma unroll
    for (int j = 0; j < 3; j++) {
        const int c = tid + j * 256;
        outp[(size_t)row * Dq + c] = (v[j] - mu) * rstd * gamma[c] + beta[c];
    }
}

// ---------------------------------------------------------------------------
// Launch
// ---------------------------------------------------------------------------
extern "C" void kernel_launch(void* const* d_in, const int* in_sizes, int n_in,
                              void* d_out, int out_size)
{
    const float* x     = (const float*)d_in[0];
    const float* Wq    = (const float*)d_in[1];
    const float* bq    = (const float*)d_in[2];
    const float* Wk    = (const float*)d_in[3];
    const float* bk    = (const float*)d_in[4];
    const float* Wv    = (const float*)d_in[5];
    const float* bv    = (const float*)d_in[6];
    const float* Wo    = (const float*)d_in[7];
    const float* bo    = (const float*)d_in[8];
    const float* gamma = (const float*)d_in[9];
    const float* beta  = (const float*)d_in[10];
    float* out = (float*)d_out;

    static int configured = 0;
    if (!configured) {
        cudaFuncSetAttribute(ig_gemm_kernel,
                             cudaFuncAttributeMaxDynamicSharedMemorySize, GEMM_SMEM);
        cudaFuncSetAttribute(attn_kernel,
                             cudaFuncAttributeMaxDynamicSharedMemorySize, ATT_SMEM);
        configured = 1;
    }

    int8_t *xq0, *xq1, *aq0, *aq1;
    float *xsc, *asc, *attp;
    cudaGetSymbolAddress((void**)&xq0, g_xq0);
    cudaGetSymbolAddress((void**)&xq1, g_xq1);
    cudaGetSymbolAddress((void**)&xsc, g_xsc);
    cudaGetSymbolAddress((void**)&aq0, g_aq0);
    cudaGetSymbolAddress((void**)&aq1, g_aq1);
    cudaGetSymbolAddress((void**)&asc, g_asc);
    cudaGetSymbolAddress((void**)&attp, g_att);

    // 0) quantize inputs + weights
    quant_rows_kernel<<<Mq, 256>>>(x, xq0, xq1, xsc);
    wmax_zero_kernel<<<12, 256>>>();
    wmax_kernel<<<dim3(3, 8, 4), 256>>>(Wq, Wk, Wv, Wo);
    wquant_kernel<<<dim3(24, 24, 4), 256>>>(Wq, Wk, Wv, Wo);

    // 1) QKV projections (N = 2304 over 18 tiles)
    ig_gemm_kernel<<<dim3(18, Mq / BM), 256, GEMM_SMEM>>>(
        xq0, xq1, xsc, bq, bk, bv, nullptr, 0, 0);

    // 2) Banded local attention -> g_att fp32
    attn_kernel<<<dim3(Sq / AT_TS, Bq * Hq), 256, ATT_SMEM>>>(bk, bv);

    // 3) quantize att, then output projection + bias + residual -> g_Y
    quant_rows_kernel<<<Mq, 256>>>(attp, aq0, aq1, asc);
    ig_gemm_kernel<<<dim3(6, Mq / BM), 256, GEMM_SMEM>>>(
        aq0, aq1, asc, bo, nullptr, nullptr, x, 3 * Dq, 1);

    // 4) LayerNorm -> d_out
    ln_kernel<<<Mq, 256>>>(gamma, beta, out);
}

// round 5
// speedup vs baseline: 3.1249x; 1.0517x over previous
#include <cuda_runtime.h>
#include <cuda_fp16.h>
#include <cstdint>

// Problem constants
#define Bq 8
#define Sq 4096
#define Dq 768
#define Hq 12
#define DHq 64
#define Mq (Bq * Sq)          // 32768 rows

// int8 GEMM tiling (mma.sync m16n8k32 s8 -> s32)
#define BM 128
#define BN 128
#define BK 64                 // int8 K elements per chunk
#define NCHUNK 12             // 768/64
#define ROWB 80               // smem row stride bytes (64 + 16 pad)
#define MAT_B (128 * ROWB)    // 10240 bytes per matrix tile
#define STAGE_B (4 * MAT_B)   // A0,A1,B0,B1 = 40960
#define NSTAGE 3
#define GEMM_SMEM (NSTAGE * STAGE_B)   // 122880

#define QMAX 16256.0f         // 127*128

// ---------------------------------------------------------------------------
// Scratch (device globals)
// ---------------------------------------------------------------------------
__device__ float g_Q[(size_t)Mq * Dq];
__device__ float g_K[(size_t)Mq * Dq];
__device__ float g_V[(size_t)Mq * Dq];
__device__ float g_att[(size_t)Mq * Dq];
__device__ float g_Y[(size_t)Mq * Dq];
__device__ int8_t g_xq0[(size_t)Mq * Dq];
__device__ int8_t g_xq1[(size_t)Mq * Dq];
__device__ float  g_xsc[Mq];
__device__ int8_t g_aq0[(size_t)Mq * Dq];
__device__ int8_t g_aq1[(size_t)Mq * Dq];
__device__ float  g_asc[Mq];
__device__ unsigned int g_amax[Mq];
__device__ int8_t g_wq0[(size_t)4 * Dq * Dq];   // transposed [n][k]; rows: Wq|Wk|Wv|Wo
__device__ int8_t g_wq1[(size_t)4 * Dq * Dq];
__device__ float  g_wsc[4 * Dq];
__device__ unsigned int g_wmax[4 * Dq];

// ---------------------------------------------------------------------------
// PTX helpers
// ---------------------------------------------------------------------------
__device__ __forceinline__ uint32_t smem_u32(const void* p) {
    uint32_t a;
    asm("{ .reg .u64 t; cvta.to.shared.u64 t, %1; cvt.u32.u64 %0, t; }" : "=r"(a) : "l"(p));
    return a;
}
__device__ __forceinline__ void cp16(uint32_t dst, const void* src) {
    asm volatile("cp.async.cg.shared.global [%0], [%1], 16;" :: "r"(dst), "l"(src) : "memory");
}
__device__ __forceinline__ void cp_commit() { asm volatile("cp.async.commit_group;" ::: "memory"); }
__device__ __forceinline__ void cp_wait1()  { asm volatile("cp.async.wait_group 1;" ::: "memory"); }
__device__ __forceinline__ void cp_wait0()  { asm volatile("cp.async.wait_group 0;" ::: "memory"); }

__device__ __forceinline__ void ldsm_x4(uint32_t (&r)[4], uint32_t addr) {
    asm volatile("ldmatrix.sync.aligned.m8n8.x4.shared.b16 {%0,%1,%2,%3}, [%4];"
                 : "=r"(r[0]), "=r"(r[1]), "=r"(r[2]), "=r"(r[3]) : "r"(addr));
}
// D += A(s8 m16k32) * B(s8 n8k32), s32 accumulate
__device__ __forceinline__ void imma(int (&d)[4], const uint32_t (&a)[4],
                                     uint32_t b0, uint32_t b1) {
    asm volatile("mma.sync.aligned.m16n8k32.row.col.s32.s8.s8.s32 "
                 "{%0,%1,%2,%3}, {%4,%5,%6,%7}, {%8,%9}, {%0,%1,%2,%3};"
                 : "+r"(d[0]), "+r"(d[1]), "+r"(d[2]), "+r"(d[3])
                 : "r"(a[0]), "r"(a[1]), "r"(a[2]), "r"(a[3]), "r"(b0), "r"(b1));
}

// ---------------------------------------------------------------------------
// Row quantizer (with block reduce): per-row absmax -> 2-digit int8
// ---------------------------------------------------------------------------
__global__ void __launch_bounds__(256) quant_rows_kernel(
    const float* __restrict__ src, int8_t* __restrict__ q0,
    int8_t* __restrict__ q1, float* __restrict__ scl)
{
    const int row = blockIdx.x;
    const int tid = threadIdx.x;
    const float* s = src + (size_t)row * Dq;

    float v[3], mx = 0.f;
    #pragma unroll
    for (int j = 0; j < 3; j++) {
        v[j] = s[tid + j * 256];
        mx = fmaxf(mx, fabsf(v[j]));
    }
    #pragma unroll
    for (int o = 16; o > 0; o >>= 1)
        mx = fmaxf(mx, __shfl_xor_sync(0xFFFFFFFFu, mx, o));
    __shared__ float rm[8];
    if ((tid & 31) == 0) rm[tid >> 5] = mx;
    __syncthreads();
    mx = fmaxf(fmaxf(fmaxf(rm[0], rm[1]), fmaxf(rm[2], rm[3])),
               fmaxf(fmaxf(rm[4], rm[5]), fmaxf(rm[6], rm[7])));

    const float inv = (mx > 0.f) ? (QMAX / mx) : 0.f;
    if (tid == 0) scl[row] = (mx > 0.f) ? (mx / QMAX) : 0.f;

    #pragma unroll
    for (int j = 0; j < 3; j++) {
        const int c = tid + j * 256;
        const int n = __float2int_rn(v[j] * inv);
        const int a0 = (n + 64) >> 7;
        const int a1 = n - (a0 << 7);
        q0[(size_t)row * Dq + c] = (int8_t)a0;
        q1[(size_t)row * Dq + c] = (int8_t)a1;
    }
}

// ---------------------------------------------------------------------------
// Elementwise quantizer using precomputed absmax (from attention atomics)
// ---------------------------------------------------------------------------
__global__ void __launch_bounds__(256) quant_att_kernel(
    const float* __restrict__ src, int8_t* __restrict__ q0,
    int8_t* __restrict__ q1, float* __restrict__ scl)
{
    const int row = blockIdx.x;
    const int tid = threadIdx.x;
    const float mx = __uint_as_float(g_amax[row]);
    const float inv = (mx > 0.f) ? (QMAX / mx) : 0.f;
    if (tid == 0) scl[row] = (mx > 0.f) ? (mx / QMAX) : 0.f;

    const float* s = src + (size_t)row * Dq;
    #pragma unroll
    for (int j = 0; j < 3; j++) {
        const int c = tid + j * 256;
        const int n = __float2int_rn(s[c] * inv);
        const int a0 = (n + 64) >> 7;
        const int a1 = n - (a0 << 7);
        q0[(size_t)row * Dq + c] = (int8_t)a0;
        q1[(size_t)row * Dq + c] = (int8_t)a1;
    }
}

__global__ void __launch_bounds__(256) zero_amax_kernel() {
    const int i = blockIdx.x * 256 + threadIdx.x;
    if (i < Mq) g_amax[i] = 0u;
}

// ---------------------------------------------------------------------------
// Weight absmax per output column (atomicMax on positive float bits)
// ---------------------------------------------------------------------------
__global__ void __launch_bounds__(256) wmax_zero_kernel() {
    const int i = blockIdx.x * 256 + threadIdx.x;
    if (i < 4 * Dq) g_wmax[i] = 0u;
}
__global__ void __launch_bounds__(256) wmax_kernel(
    const float* __restrict__ Wq, const float* __restrict__ Wk,
    const float* __restrict__ Wv, const float* __restrict__ Wo)
{
    const int w = blockIdx.z;
    const float* W = (w == 0) ? Wq : (w == 1) ? Wk : (w == 2) ? Wv : Wo;
    const int n = blockIdx.x * 256 + threadIdx.x;
    const int k0 = blockIdx.y * 96;
    float mx = 0.f;
    for (int j = 0; j < 96; j++)
        mx = fmaxf(mx, fabsf(W[(size_t)(k0 + j) * Dq + n]));
    atomicMax(&g_wmax[w * Dq + n], __float_as_uint(mx));
}

// ---------------------------------------------------------------------------
// Weight quantize + transpose: out[n][k] digits
// ---------------------------------------------------------------------------
__global__ void __launch_bounds__(256) wquant_kernel(
    const float* __restrict__ Wq, const float* __restrict__ Wk,
    const float* __restrict__ Wv, const float* __restrict__ Wo)
{
    __shared__ float t[32][33];
    const int w = blockIdx.z;
    const float* W = (w == 0) ? Wq : (w == 1) ? Wk : (w == 2) ? Wv : Wo;
    const int n0 = blockIdx.x * 32, k0 = blockIdx.y * 32;
    const int tx = threadIdx.x & 31, ty = threadIdx.x >> 5;

    #pragma unroll
    for (int i = 0; i < 4; i++)
        t[ty + i * 8][tx] = W[(size_t)(k0 + ty + i * 8) * Dq + n0 + tx];
    __syncthreads();
    #pragma unroll
    for (int i = 0; i < 4; i++) {
        const int n = n0 + ty + i * 8;
        const float mx = __uint_as_float(g_wmax[w * Dq + n]);
        const float inv = (mx > 0.f) ? (QMAX / mx) : 0.f;
        if (k0 == 0 && tx == 0)
            g_wsc[w * Dq + n] = (mx > 0.f) ? (mx / QMAX) : 0.f;
        const float val = t[tx][ty + i * 8];        // W[k0+tx][n]
        const int q = __float2int_rn(val * inv);
        const int a0 = (q + 64) >> 7;
        const int a1 = q - (a0 << 7);
        const size_t o = (size_t)(w * Dq + n) * Dq + k0 + tx;
        g_wq0[o] = (int8_t)a0;
        g_wq1[o] = (int8_t)a1;
    }
}

// ---------------------------------------------------------------------------
// int8 tensor-core GEMM: C = A @ W^T, 2-digit emulation, 3 products.
// mode 0: outputs Q|K|V (+bias), grid (18, 256)
// mode 1: g_Y = C + bo + resid, grid (6, 256)
// ---------------------------------------------------------------------------
__global__ void __launch_bounds__(256, 1) ig_gemm_kernel(
    const int8_t* __restrict__ Aq0, const int8_t* __restrict__ Aq1,
    const float* __restrict__ Asc,
    const float* __restrict__ bias_a, const float* __restrict__ bias_b,
    const float* __restrict__ bias_c, const float* __restrict__ resid,
    int wbase, int mode)
{
    extern __shared__ __align__(128) char smem_raw[];
    const uint32_t base = smem_u32(smem_raw);

    const int tid  = threadIdx.x;
    const int wid  = tid >> 5;
    const int lane = tid & 31;
    const int m0 = blockIdx.y * BM;
    const int bx = blockIdx.x;
    const int nrow0 = wbase + bx * BN;

    const int wm0 = (wid & 3) * 32;          // 4 warps in M
    const int wn0 = (wid >> 2) * 64;         // 2 warps in N

    auto load_stage = [&](int c, int s) {
        const int k0 = c * BK;
        const uint32_t sb = base + (uint32_t)s * STAGE_B;
        #pragma unroll
        for (int half = 0; half < 2; half++) {
            const int u = tid + half * 256;          // 0..511
            const int row = u >> 2, seg = (u & 3) * 16;
            const uint32_t so = (uint32_t)(row * ROWB + seg);
            cp16(sb + 0 * MAT_B + so, Aq0 + (size_t)(m0 + row) * Dq + k0 + seg);
            cp16(sb + 1 * MAT_B + so, Aq1 + (size_t)(m0 + row) * Dq + k0 + seg);
            cp16(sb + 2 * MAT_B + so, g_wq0 + (size_t)(nrow0 + row) * Dq + k0 + seg);
            cp16(sb + 3 * MAT_B + so, g_wq1 + (size_t)(nrow0 + row) * Dq + k0 + seg);
        }
        cp_commit();
    };

    int hi[2][8][4], mid[2][8][4];
    #pragma unroll
    for (int mi = 0; mi < 2; mi++)
        #pragma unroll
        for (int n8 = 0; n8 < 8; n8++)
            #pragma unroll
            for (int j = 0; j < 4; j++) { hi[mi][n8][j] = 0; mid[mi][n8][j] = 0; }

    const int lrow = (lane & 7) + ((lane >> 3) & 1) * 8;
    const int lk16 = (lane >> 4) * 16;

    load_stage(0, 0);
    load_stage(1, 1);

    for (int c = 0; c < NCHUNK; c++) {
        if (c + 1 < NCHUNK) cp_wait1();   // pending: {L_c, L_{c+1}} -> ensure L_c
        else                cp_wait0();   // last chunk: only L_c pending, drain it
        __syncthreads();
        if (c + 2 < NCHUNK) load_stage(c + 2, (c + 2) % NSTAGE);

        const uint32_t sb = base + (uint32_t)(c % NSTAGE) * STAGE_B;
        const uint32_t sA0 = sb, sA1 = sb + MAT_B, sB0 = sb + 2 * MAT_B, sB1 = sb + 3 * MAT_B;

        #pragma unroll
        for (int ks = 0; ks < 2; ks++) {
            const uint32_t koff = (uint32_t)(ks * 32 + lk16);
            uint32_t a0[2][4], a1[2][4];
            #pragma unroll
            for (int mi = 0; mi < 2; mi++) {
                const uint32_t ro = (uint32_t)((wm0 + mi * 16 + lrow) * ROWB) + koff;
                ldsm_x4(a0[mi], sA0 + ro);
                ldsm_x4(a1[mi], sA1 + ro);
            }
            #pragma unroll
            for (int g = 0; g < 4; g++) {
                uint32_t b0[4], b1[4];
                const uint32_t ro = (uint32_t)((wn0 + g * 16 + lrow) * ROWB) + koff;
                ldsm_x4(b0, sB0 + ro);
                ldsm_x4(b1, sB1 + ro);
                #pragma unroll
                for (int mi = 0; mi < 2; mi++) {
                    imma(hi[mi][g * 2 + 0], a0[mi], b0[0], b0[2]);
                    imma(hi[mi][g * 2 + 1], a0[mi], b0[1], b0[3]);
                    imma(mid[mi][g * 2 + 0], a0[mi], b1[0], b1[2]);
                    imma(mid[mi][g * 2 + 1], a0[mi], b1[1], b1[3]);
                    imma(mid[mi][g * 2 + 0], a1[mi], b0[0], b0[2]);
                    imma(mid[mi][g * 2 + 1], a1[mi], b0[1], b0[3]);
                }
            }
        }
    }

    // ---- epilogue ----
    float* outp;
    const float* bias;
    int n0in;
    if (mode == 0) {
        const int sel = bx / 6;
        n0in = (bx % 6) * BN;
        outp = (sel == 0) ? g_Q : (sel == 1) ? g_K : g_V;
        bias = (sel == 0) ? bias_a : (sel == 1) ? bias_b : bias_c;
    } else {
        n0in = bx * BN;
        outp = g_Y;
        bias = bias_a;
    }

    const int qr = lane >> 2;
    const int qc = (lane & 3) * 2;
    #pragma unroll
    for (int mi = 0; mi < 2; mi++) {
        #pragma unroll
        for (int half = 0; half < 2; half++) {
            const int m = m0 + wm0 + mi * 16 + qr + half * 8;
            const float sa128 = Asc[m] * 128.f;
            #pragma unroll
            for (int n8 = 0; n8 < 8; n8++) {
                const int nl = wn0 + n8 * 8 + qc;
                const float sb0 = g_wsc[nrow0 + nl] * sa128;
                const float sb1 = g_wsc[nrow0 + nl + 1] * sa128;
                const int n = n0in + nl;
                const size_t o = (size_t)m * Dq + n;
                const int t0 = hi[mi][n8][half * 2 + 0] * 128 + mid[mi][n8][half * 2 + 0];
                const int t1 = hi[mi][n8][half * 2 + 1] * 128 + mid[mi][n8][half * 2 + 1];
                float2 v;
                v.x = (float)t0 * sb0 + bias[n];
                v.y = (float)t1 * sb1 + bias[n + 1];
                if (mode == 1) {
                    v.x += resid[o];
                    v.y += resid[o + 1];
                }
                *(float2*)(outp + o) = v;
            }
        }
    }
}

// ---------------------------------------------------------------------------
// Banded attention v3: 2 threads per position (each owns 32 dims),
// fp16 K/V smem staging (18.5 KB), fused absmax atomics for quantization.
// ---------------------------------------------------------------------------
#define AT_TS 128
#define AT_HALO 132
#define AT_ROWH 70            // halves per row stride (140 B -> conflict-free half2)
#define ATT_SMEM (AT_HALO * AT_ROWH * 2)   // 18480 B

__global__ void __launch_bounds__(256) attn_kernel(
    const float* __restrict__ bk, const float* __restrict__ bv)
{
    extern __shared__ __half smh[];

    const int by = blockIdx.y;
    const int b  = by / Hq;
    const int h  = by % Hq;
    const int s0 = blockIdx.x * AT_TS;

    const size_t basep = ((size_t)b * Sq) * Dq + h * DHq;
    const int tid = threadIdx.x;
    const int si  = tid >> 1;          // position within tile
    const int hh  = tid & 1;           // dim half (0: dims 0-31, 1: dims 32-63)

    // ---- stage K (fp16) ----
    {
        const float* Kg = g_K + basep;
        const float* bsrc = bk + h * DHq;
        for (int idx = tid; idx < AT_HALO * 32; idx += 256) {
            const int r = idx >> 5;            // halo row 0..131
            const int c2 = (idx & 31) * 2;     // dim pair
            const int gs = s0 - 2 + r;
            float2 v = (gs >= 0 && gs < Sq)
                       ? *(const float2*)(Kg + (size_t)gs * Dq + c2)
                       : *(const float2*)(bsrc + c2);
            *(__half2*)&smh[r * AT_ROWH + c2] = __float22half2_rn(v);
        }
    }
    __syncthreads();

    // q for this thread's 32 dims
    const float* qrow = g_Q + ((size_t)b * Sq + s0 + si) * Dq + h * DHq + hh * 32;
    float2 qv[16];
    #pragma unroll
    for (int d2 = 0; d2 < 16; d2++) qv[d2] = *(const float2*)(qrow + 2 * d2);

    float sc[5];
    #pragma unroll
    for (int i = 0; i < 5; i++) {
        const __half2* krow = (const __half2*)&smh[(si + i) * AT_ROWH + hh * 32];
        float s = 0.f;
        #pragma unroll
        for (int d2 = 0; d2 < 16; d2++) {
            const float2 kf = __half22float2(krow[d2]);
            s += qv[d2].x * kf.x + qv[d2].y * kf.y;
        }
        sc[i] = s;
    }
    // combine the two dim-halves (partner lane = tid ^ 1, same warp)
    #pragma unroll
    for (int i = 0; i < 5; i++)
        sc[i] += __shfl_xor_sync(0xFFFFFFFFu, sc[i], 1);

    float mx = sc[0];
    #pragma unroll
    for (int i = 1; i < 5; i++) mx = fmaxf(mx, sc[i]);
    float p[5], sum = 0.f;
    #pragma unroll
    for (int i = 0; i < 5; i++) {
        p[i] = __expf((sc[i] - mx) * 0.125f);
        sum += p[i];
    }
    const float inv = 1.f / sum;
    #pragma unroll
    for (int i = 0; i < 5; i++) p[i] *= inv;

    // ---- stage V (reuse smem) ----
    __syncthreads();
    {
        const float* Vg = g_V + basep;
        const float* bsrc = bv + h * DHq;
        for (int idx = tid; idx < AT_HALO * 32; idx += 256) {
            const int r = idx >> 5;
            const int c2 = (idx & 31) * 2;
            const int gs = s0 - 2 + r;
            float2 v = (gs >= 0 && gs < Sq)
                       ? *(const float2*)(Vg + (size_t)gs * Dq + c2)
                       : *(const float2*)(bsrc + c2);
            *(__half2*)&smh[r * AT_ROWH + c2] = __float22half2_rn(v);
        }
    }
    __syncthreads();

    float2 o2[16];
    #pragma unroll
    for (int d2 = 0; d2 < 16; d2++) { o2[d2].x = 0.f; o2[d2].y = 0.f; }
    #pragma unroll
    for (int i = 0; i < 5; i++) {
        const __half2* vrow = (const __half2*)&smh[(si + i) * AT_ROWH + hh * 32];
        const float pi = p[i];
        #pragma unroll
        for (int d2 = 0; d2 < 16; d2++) {
            const float2 vf = __half22float2(vrow[d2]);
            o2[d2].x += pi * vf.x;
            o2[d2].y += pi * vf.y;
        }
    }

    const int row = b * Sq + s0 + si;
    float* orow = g_att + (size_t)row * Dq + h * DHq + hh * 32;
    float amx = 0.f;
    #pragma unroll
    for (int d2 = 0; d2 < 16; d2++) {
        *(float2*)(orow + 2 * d2) = o2[d2];
        amx = fmaxf(amx, fmaxf(fabsf(o2[d2].x), fabsf(o2[d2].y)));
    }
    atomicMax(&g_amax[row], __float_as_uint(amx));
}

// ---------------------------------------------------------------------------
// LayerNorm over last dim (768)
// ---------------------------------------------------------------------------
__global__ void __launch_bounds__(256) ln_kernel(
    const float* __restrict__ gamma, const float* __restrict__ beta,
    float* __restrict__ outp)
{
    const int row = blockIdx.x;
    const float* y = g_Y + (size_t)row * Dq;
    const int tid = threadIdx.x;

    float v[3];
    float s = 0.f, ss = 0.f;
    #pragma unroll
    for (int j = 0; j < 3; j++) {
        v[j] = y[tid + j * 256];
        s  += v[j];
        ss += v[j] * v[j];
    }
    #pragma unroll
    for (int o = 16; o > 0; o >>= 1) {
        s  += __shfl_xor_sync(0xFFFFFFFFu, s,  o);
        ss += __shfl_xor_sync(0xFFFFFFFFu, ss, o);
    }
    __shared__ float rs[8], rss[8];
    const int w = tid >> 5;
    if ((tid & 31) == 0) { rs[w] = s; rss[w] = ss; }
    __syncthreads();
    s = 0.f; ss = 0.f;
    #pragma unroll
    for (int i = 0; i < 8; i++) { s += rs[i]; ss += rss[i]; }

    const float mu   = s * (1.f / 768.f);
    const float var  = ss * (1.f / 768.f) - mu * mu;
    const float rstd = rsqrtf(var + 1e-5f);

    #pragma unroll
    for (int j = 0; j < 3; j++) {
        const int c = tid + j * 256;
        outp[(size_t)row * Dq + c] = (v[j] - mu) * rstd * gamma[c] + beta[c];
    }
}

// ---------------------------------------------------------------------------
// Launch
// ---------------------------------------------------------------------------
extern "C" void kernel_launch(void* const* d_in, const int* in_sizes, int n_in,
                              void* d_out, int out_size)
{
    const float* x     = (const float*)d_in[0];
    const float* Wq    = (const float*)d_in[1];
    const float* bq    = (const float*)d_in[2];
    const float* Wk    = (const float*)d_in[3];
    const float* bk    = (const float*)d_in[4];
    const float* Wv    = (const float*)d_in[5];
    const float* bv    = (const float*)d_in[6];
    const float* Wo    = (const float*)d_in[7];
    const float* bo    = (const float*)d_in[8];
    const float* gamma = (const float*)d_in[9];
    const float* beta  = (const float*)d_in[10];
    float* out = (float*)d_out;

    static int configured = 0;
    if (!configured) {
        cudaFuncSetAttribute(ig_gemm_kernel,
                             cudaFuncAttributeMaxDynamicSharedMemorySize, GEMM_SMEM);
        cudaFuncSetAttribute(attn_kernel,
                             cudaFuncAttributeMaxDynamicSharedMemorySize, ATT_SMEM);
        configured = 1;
    }

    int8_t *xq0, *xq1, *aq0, *aq1;
    float *xsc, *asc, *attp;
    cudaGetSymbolAddress((void**)&xq0, g_xq0);
    cudaGetSymbolAddress((void**)&xq1, g_xq1);
    cudaGetSymbolAddress((void**)&xsc, g_xsc);
    cudaGetSymbolAddress((void**)&aq0, g_aq0);
    cudaGetSymbolAddress((void**)&aq1, g_aq1);
    cudaGetSymbolAddress((void**)&asc, g_asc);
    cudaGetSymbolAddress((void**)&attp, g_att);

    // 0) quantize inputs + weights
    quant_rows_kernel<<<Mq, 256>>>(x, xq0, xq1, xsc);
    wmax_zero_kernel<<<12, 256>>>();
    wmax_kernel<<<dim3(3, 8, 4), 256>>>(Wq, Wk, Wv, Wo);
    wquant_kernel<<<dim3(24, 24, 4), 256>>>(Wq, Wk, Wv, Wo);
    zero_amax_kernel<<<Mq / 256, 256>>>();

    // 1) QKV projections (N = 2304 over 18 tiles)
    ig_gemm_kernel<<<dim3(18, Mq / BM), 256, GEMM_SMEM>>>(
        xq0, xq1, xsc, bq, bk, bv, nullptr, 0, 0);

    // 2) Banded local attention -> g_att fp32 + fused absmax
    attn_kernel<<<dim3(Sq / AT_TS, Bq * Hq), 256, ATT_SMEM>>>(bk, bv);

    // 3) quantize att (elementwise, absmax precomputed), then O projection
    quant_att_kernel<<<Mq, 256>>>(attp, aq0, aq1, asc);
    ig_gemm_kernel<<<dim3(6, Mq / BM), 256, GEMM_SMEM>>>(
        aq0, aq1, asc, bo, nullptr, nullptr, x, 3 * Dq, 1);

    // 4) LayerNorm -> d_out
    ln_kernel<<<Mq, 256>>>(gamma, beta, out);
}